// round 11
// baseline (speedup 1.0000x reference)
#include <cuda_runtime.h>
#include <cuda_bf16.h>
#include <cuda_fp16.h>
#include <math.h>
#include <stdint.h>
#include <utility>

// ---------------------------------------------------------------------------
// Problem constants
// ---------------------------------------------------------------------------
namespace {
constexpr int B   = 128;
constexpr int T   = 31;
constexpr int TP1 = 32;     // T+1
constexpr int E   = 512;
constexpr int H   = 512;
constexpr int V   = 10000;
constexpr int A   = 2048;
constexpr int G4  = 2048;   // 4*H
constexpr int NC  = 4096;   // comb cols: [scores | gates_h]
constexpr int MALL = TP1 * B;   // 4096
constexpr int VPAD = 10240;     // 40 * 256
constexpr int KBF  = 1536;      // 3 * 512 split-bf16 K
constexpr int KBFA = 6144;      // 3 * 2048 split-bf16 K (attd)
constexpr int KH1  = 512;       // 1-term fp16 K (logits)

// fp32 scratch layout
constexpr size_t XS_OFF   = 0;                              // [TP1][B][E]
constexpr size_t PAN_OFF  = XS_OFF  + (size_t)TP1*B*E;      // [TP1][B][A]
constexpr size_t PAD_OFF  = PAN_OFF + (size_t)TP1*B*A;      // [TP1][B][E]
constexpr size_t C_OFF    = PAD_OFF + (size_t)TP1*B*E;      // [B][H]
constexpr size_t SLC_OFF  = C_OFF   + (size_t)B*H;          // [8][B][NC]
constexpr size_t SLD_OFF  = SLC_OFF + (size_t)8*B*NC;       // [32][B][E]
constexpr size_t SLG_OFF  = SLD_OFF + (size_t)32*B*E;       // [8][B][G4]
constexpr size_t BS_OFF   = SLG_OFF + (size_t)8*B*G4;       // [G4]
constexpr size_t BUF_TOTAL = BS_OFF + (size_t)G4;
}

__device__ float g_buf[BUF_TOTAL];

// bf16 split operand buffers
__device__ __nv_bfloat16 g_xs_bf   [(size_t)MALL * KBF];   // A-side [hi|hi|lo]
__device__ __nv_bfloat16 g_wattn_bf[(size_t)A * KBF];      // B-side (pan)
__device__ __nv_bfloat16 g_wattd_bf[(size_t)E * KBF];      // B-side (pad)
__device__ __nv_bfloat16 g_h_bf    [(size_t)B * KBF];      // A-side h
__device__ __nv_bfloat16 g_att_bf  [(size_t)B * KBFA];     // A-side att
__device__ __nv_bfloat16 g_x2_bf   [(size_t)B * KBF];      // A-side x2
__device__ __nv_bfloat16 g_wcomb_bf[(size_t)NC * KBF];     // B-side comb W
__device__ __nv_bfloat16 g_wih_bf  [(size_t)G4 * KBF];     // B-side W_ih
__device__ __nv_bfloat16 g_wattd2_bf[(size_t)E * KBFA];    // B-side W_attd[:,E:]
// fp16 1-term buffers (logits)
__device__ __half g_hid_h [(size_t)MALL * KH1];
__device__ __half g_wout_h[(size_t)VPAD * KH1];

__device__ __forceinline__ void pdl_wait() {
    asm volatile("griddepcontrol.wait;" ::: "memory");
}

__device__ __forceinline__ void split_bf(float x, __nv_bfloat16& hi, __nv_bfloat16& lo) {
    hi = __float2bfloat16(x);
    lo = __float2bfloat16(x - __bfloat162float(hi));
}

// ---------------------------------------------------------------------------
// HMMA helpers (sm_80+ PTX)
// ---------------------------------------------------------------------------
__device__ __forceinline__ uint32_t smem_u32(const void* p) {
    uint32_t a;
    asm("{ .reg .u64 t; cvta.to.shared.u64 t, %1; cvt.u32.u64 %0, t; }"
        : "=r"(a) : "l"(p));
    return a;
}
__device__ __forceinline__ void cpa16(uint32_t s, const void* g) {
    asm volatile("cp.async.cg.shared.global [%0], [%1], 16;"
                 :: "r"(s), "l"(g));
}
#define CP_COMMIT() asm volatile("cp.async.commit_group;" ::: "memory")
#define CP_WAIT(N)  asm volatile("cp.async.wait_group %0;" :: "n"(N) : "memory")

#define LDSM4(R0, R1, R2, R3, ADDR) \
    asm volatile("ldmatrix.sync.aligned.m8n8.x4.shared.b16 {%0,%1,%2,%3}, [%4];" \
        : "=r"(R0), "=r"(R1), "=r"(R2), "=r"(R3) : "r"(ADDR))

template<bool FP16>
__device__ __forceinline__ void mma16816(float* d, const uint32_t* a,
                                         uint32_t b0, uint32_t b1) {
    if constexpr (FP16) {
        asm volatile(
            "mma.sync.aligned.m16n8k16.row.col.f32.f16.f16.f32 "
            "{%0,%1,%2,%3}, {%4,%5,%6,%7}, {%8,%9}, {%0,%1,%2,%3};"
            : "+f"(d[0]), "+f"(d[1]), "+f"(d[2]), "+f"(d[3])
            : "r"(a[0]), "r"(a[1]), "r"(a[2]), "r"(a[3]), "r"(b0), "r"(b1));
    } else {
        asm volatile(
            "mma.sync.aligned.m16n8k16.row.col.f32.bf16.bf16.f32 "
            "{%0,%1,%2,%3}, {%4,%5,%6,%7}, {%8,%9}, {%0,%1,%2,%3};"
            : "+f"(d[0]), "+f"(d[1]), "+f"(d[2]), "+f"(d[3])
            : "r"(a[0]), "r"(a[1]), "r"(a[2]), "r"(a[3]), "r"(b0), "r"(b1));
    }
}

namespace {
constexpr int HBK   = 32;
constexpr int HROWB = 80;             // 32 elems * 2B + 16B pad
constexpr int HSTG  = 256 * HROWB;    // 20480 B per stage (128 A + 128 B rows)
constexpr int HSMEM = 3 * HSTG;       // 61440 B
constexpr int HSTG2 = 384 * HROWB;    // 30720 B per stage (128 A + 256 B rows)
constexpr int HSMEM2 = 3 * HSTG2;     // 92160 B
}

// ---------------------------------------------------------------------------
// hmma_gemm: 128x128 tile (pad GEMM). Compile-time K.
// ---------------------------------------------------------------------------
template<int KTOT, bool FP16>
__global__ void __launch_bounds__(256, 2)
hmma_gemm(float* __restrict__ C, int ldc, int Nreal,
          const uint16_t* __restrict__ Abf,
          const uint16_t* __restrict__ Bbf,
          const float* __restrict__ bias)
{
    pdl_wait();
    constexpr int NT = KTOT / HBK;
    extern __shared__ __align__(16) char sm[];
    const uint32_t sb = smem_u32(sm);

    const int tid  = threadIdx.x;
    const int wid  = tid >> 5;
    const int lane = tid & 31;
    const int wm   = wid & 1;
    const int wn   = wid >> 1;
    const int row0 = blockIdx.y * 128;
    const int col0 = blockIdx.x * 128;

    const int qr0 = (tid)       >> 2, qc0 = (tid)       & 3;
    const int qr1 = (tid + 256) >> 2, qc1 = (tid + 256) & 3;

    auto LOADG = [&](int t, int stg) {
        const int k0 = t * HBK;
        const uint32_t sa  = sb + stg * HSTG;
        const uint32_t sbm = sa + 128 * HROWB;
        cpa16(sa  + qr0 * HROWB + qc0 * 16,
              Abf + (size_t)(row0 + qr0) * KTOT + k0 + qc0 * 8);
        cpa16(sa  + qr1 * HROWB + qc1 * 16,
              Abf + (size_t)(row0 + qr1) * KTOT + k0 + qc1 * 8);
        cpa16(sbm + qr0 * HROWB + qc0 * 16,
              Bbf + (size_t)(col0 + qr0) * KTOT + k0 + qc0 * 8);
        cpa16(sbm + qr1 * HROWB + qc1 * 16,
              Bbf + (size_t)(col0 + qr1) * KTOT + k0 + qc1 * 8);
    };

    float acc[4][4][4];
#pragma unroll
    for (int i = 0; i < 4; ++i)
#pragma unroll
        for (int j = 0; j < 4; ++j)
#pragma unroll
            for (int q = 0; q < 4; ++q) acc[i][j][q] = 0.f;

    const int lr  = lane & 15;
    const int lkb = (lane >> 4) * 16;

    LOADG(0, 0); CP_COMMIT();
    LOADG(1, 1); CP_COMMIT();

    for (int t = 0; t < NT; ++t) {
        if (t + 1 < NT) { CP_WAIT(1); } else { CP_WAIT(0); }
        __syncthreads();
        if (t + 2 < NT) { LOADG(t + 2, (t + 2) % 3); CP_COMMIT(); }

        const uint32_t aB = sb + (t % 3) * HSTG;
        const uint32_t bB = aB + 128 * HROWB;
#pragma unroll
        for (int ks = 0; ks < 2; ++ks) {
            const int kbyte = ks * 32 + lkb;
            uint32_t af[4][4];
#pragma unroll
            for (int mf = 0; mf < 4; ++mf)
                LDSM4(af[mf][0], af[mf][1], af[mf][2], af[mf][3],
                      aB + (wm * 64 + mf * 16 + lr) * HROWB + kbyte);
            uint32_t bfr[2][4];
#pragma unroll
            for (int p = 0; p < 2; ++p)
                LDSM4(bfr[p][0], bfr[p][1], bfr[p][2], bfr[p][3],
                      bB + (wn * 32 + p * 16 + lr) * HROWB + kbyte);
#pragma unroll
            for (int mf = 0; mf < 4; ++mf)
#pragma unroll
                for (int nf = 0; nf < 4; ++nf)
                    mma16816<FP16>(acc[mf][nf], af[mf],
                                   bfr[nf >> 1][nf & 1], bfr[nf >> 1][(nf & 1) + 2]);
        }
    }

    const int rbase = row0 + wm * 64 + (lane >> 2);
    const int cbase = col0 + wn * 32 + 2 * (lane & 3);
#pragma unroll
    for (int nf = 0; nf < 4; ++nf) {
        const int col = cbase + nf * 8;
        if (col >= Nreal) continue;
        const float2 bv = *reinterpret_cast<const float2*>(bias + col);
#pragma unroll
        for (int mf = 0; mf < 4; ++mf) {
            const int r = rbase + mf * 16;
            *reinterpret_cast<float2*>(C + (size_t)r * ldc + col) =
                make_float2(acc[mf][nf][0] + bv.x, acc[mf][nf][1] + bv.y);
            *reinterpret_cast<float2*>(C + (size_t)(r + 8) * ldc + col) =
                make_float2(acc[mf][nf][2] + bv.x, acc[mf][nf][3] + bv.y);
        }
    }
}

// ---------------------------------------------------------------------------
// hmma_gemm2: 128x256 tile (logits / pan). Higher mma:ldmatrix ratio.
// 256 threads, warp tile 64x64, 3-stage cp.async, 92 KB dyn smem, 1 CTA/SM.
// ---------------------------------------------------------------------------
template<int KTOT, bool FP16>
__global__ void __launch_bounds__(256, 1)
hmma_gemm2(float* __restrict__ C, int ldc, int Nreal,
           const uint16_t* __restrict__ Abf,
           const uint16_t* __restrict__ Bbf,
           const float* __restrict__ bias)
{
    pdl_wait();
    constexpr int NT = KTOT / HBK;
    extern __shared__ __align__(16) char sm[];
    const uint32_t sb = smem_u32(sm);

    const int tid  = threadIdx.x;
    const int wid  = tid >> 5;
    const int lane = tid & 31;
    const int wm   = wid & 1;        // 2 warp rows (64 each)
    const int wn   = wid >> 1;       // 4 warp cols (64 each)
    const int row0 = blockIdx.y * 128;
    const int col0 = blockIdx.x * 256;

    // A: 512 16B-chunks (2/thread), B: 1024 chunks (4/thread)
    const int qr0 = (tid)       >> 2, qc0 = (tid)       & 3;
    const int qr1 = (tid + 256) >> 2, qc1 = (tid + 256) & 3;

    auto LOADG = [&](int t, int stg) {
        const int k0 = t * HBK;
        const uint32_t sa  = sb + stg * HSTG2;
        const uint32_t sbm = sa + 128 * HROWB;
        cpa16(sa + qr0 * HROWB + qc0 * 16,
              Abf + (size_t)(row0 + qr0) * KTOT + k0 + qc0 * 8);
        cpa16(sa + qr1 * HROWB + qc1 * 16,
              Abf + (size_t)(row0 + qr1) * KTOT + k0 + qc1 * 8);
#pragma unroll
        for (int i = 0; i < 4; ++i) {
            int idx = tid + i * 256;
            int r = idx >> 2, cq = idx & 3;
            cpa16(sbm + r * HROWB + cq * 16,
                  Bbf + (size_t)(col0 + r) * KTOT + k0 + cq * 8);
        }
    };

    float acc[4][8][4];
#pragma unroll
    for (int i = 0; i < 4; ++i)
#pragma unroll
        for (int j = 0; j < 8; ++j)
#pragma unroll
            for (int q = 0; q < 4; ++q) acc[i][j][q] = 0.f;

    const int lr  = lane & 15;
    const int lkb = (lane >> 4) * 16;

    LOADG(0, 0); CP_COMMIT();
    LOADG(1, 1); CP_COMMIT();

    for (int t = 0; t < NT; ++t) {
        if (t + 1 < NT) { CP_WAIT(1); } else { CP_WAIT(0); }
        __syncthreads();
        if (t + 2 < NT) { LOADG(t + 2, (t + 2) % 3); CP_COMMIT(); }

        const uint32_t aB = sb + (t % 3) * HSTG2;
        const uint32_t bB = aB + 128 * HROWB;
#pragma unroll
        for (int ks = 0; ks < 2; ++ks) {
            const int kbyte = ks * 32 + lkb;
            uint32_t af[4][4];
#pragma unroll
            for (int mf = 0; mf < 4; ++mf)
                LDSM4(af[mf][0], af[mf][1], af[mf][2], af[mf][3],
                      aB + (wm * 64 + mf * 16 + lr) * HROWB + kbyte);
            uint32_t bfr[4][4];
#pragma unroll
            for (int p = 0; p < 4; ++p)
                LDSM4(bfr[p][0], bfr[p][1], bfr[p][2], bfr[p][3],
                      bB + (wn * 64 + p * 16 + lr) * HROWB + kbyte);
#pragma unroll
            for (int mf = 0; mf < 4; ++mf)
#pragma unroll
                for (int nf = 0; nf < 8; ++nf)
                    mma16816<FP16>(acc[mf][nf], af[mf],
                                   bfr[nf >> 1][nf & 1], bfr[nf >> 1][(nf & 1) + 2]);
        }
    }

    const int rbase = row0 + wm * 64 + (lane >> 2);
    const int cbase = col0 + wn * 64 + 2 * (lane & 3);
#pragma unroll
    for (int nf = 0; nf < 8; ++nf) {
        const int col = cbase + nf * 8;
        if (col >= Nreal) continue;
        const float2 bv = *reinterpret_cast<const float2*>(bias + col);
#pragma unroll
        for (int mf = 0; mf < 4; ++mf) {
            const int r = rbase + mf * 16;
            *reinterpret_cast<float2*>(C + (size_t)r * ldc + col) =
                make_float2(acc[mf][nf][0] + bv.x, acc[mf][nf][1] + bv.y);
            *reinterpret_cast<float2*>(C + (size_t)(r + 8) * ldc + col) =
                make_float2(acc[mf][nf][2] + bv.x, acc[mf][nf][3] + bv.y);
        }
    }
}

// ---------------------------------------------------------------------------
// hmma_rec: recurrent-step GEMM. M = 128, runtime K range, split-K slabs.
// ---------------------------------------------------------------------------
__global__ void __launch_bounds__(256, 2)
hmma_rec(float* __restrict__ C, int N,
         const uint16_t* __restrict__ Abf,
         const uint16_t* __restrict__ Bbf, int lda,
         int KC)
{
    pdl_wait();
    extern __shared__ __align__(16) char sm[];
    const uint32_t sb = smem_u32(sm);

    const int NT   = KC / HBK;
    const int kbeg = blockIdx.z * KC;
    const int tid  = threadIdx.x;
    const int wid  = tid >> 5;
    const int lane = tid & 31;
    const int wm   = wid & 1;
    const int wn   = wid >> 1;
    const int col0 = blockIdx.x * 128;
    float* Cz = C + (size_t)blockIdx.z * 128 * N;

    const int qr0 = (tid)       >> 2, qc0 = (tid)       & 3;
    const int qr1 = (tid + 256) >> 2, qc1 = (tid + 256) & 3;

    auto LOADG = [&](int t, int stg) {
        const int k0 = kbeg + t * HBK;
        const uint32_t sa  = sb + stg * HSTG;
        const uint32_t sbm = sa + 128 * HROWB;
        cpa16(sa  + qr0 * HROWB + qc0 * 16,
              Abf + (size_t)qr0 * lda + k0 + qc0 * 8);
        cpa16(sa  + qr1 * HROWB + qc1 * 16,
              Abf + (size_t)qr1 * lda + k0 + qc1 * 8);
        cpa16(sbm + qr0 * HROWB + qc0 * 16,
              Bbf + (size_t)(col0 + qr0) * lda + k0 + qc0 * 8);
        cpa16(sbm + qr1 * HROWB + qc1 * 16,
              Bbf + (size_t)(col0 + qr1) * lda + k0 + qc1 * 8);
    };

    float acc[4][4][4];
#pragma unroll
    for (int i = 0; i < 4; ++i)
#pragma unroll
        for (int j = 0; j < 4; ++j)
#pragma unroll
            for (int q = 0; q < 4; ++q) acc[i][j][q] = 0.f;

    const int lr  = lane & 15;
    const int lkb = (lane >> 4) * 16;

    LOADG(0, 0); CP_COMMIT();
    LOADG(1, 1); CP_COMMIT();

    for (int t = 0; t < NT; ++t) {
        if (t + 1 < NT) { CP_WAIT(1); } else { CP_WAIT(0); }
        __syncthreads();
        if (t + 2 < NT) { LOADG(t + 2, (t + 2) % 3); CP_COMMIT(); }

        const uint32_t aB = sb + (t % 3) * HSTG;
        const uint32_t bB = aB + 128 * HROWB;
#pragma unroll
        for (int ks = 0; ks < 2; ++ks) {
            const int kbyte = ks * 32 + lkb;
            uint32_t af[4][4];
#pragma unroll
            for (int mf = 0; mf < 4; ++mf)
                LDSM4(af[mf][0], af[mf][1], af[mf][2], af[mf][3],
                      aB + (wm * 64 + mf * 16 + lr) * HROWB + kbyte);
            uint32_t bfr[2][4];
#pragma unroll
            for (int p = 0; p < 2; ++p)
                LDSM4(bfr[p][0], bfr[p][1], bfr[p][2], bfr[p][3],
                      bB + (wn * 32 + p * 16 + lr) * HROWB + kbyte);
#pragma unroll
            for (int mf = 0; mf < 4; ++mf)
#pragma unroll
                for (int nf = 0; nf < 4; ++nf)
                    mma16816<false>(acc[mf][nf], af[mf],
                                    bfr[nf >> 1][nf & 1], bfr[nf >> 1][(nf & 1) + 2]);
        }
    }

    const int rbase = wm * 64 + (lane >> 2);
    const int cbase = col0 + wn * 32 + 2 * (lane & 3);
#pragma unroll
    for (int nf = 0; nf < 4; ++nf) {
        const int col = cbase + nf * 8;
#pragma unroll
        for (int mf = 0; mf < 4; ++mf) {
            const int r = rbase + mf * 16;
            *reinterpret_cast<float2*>(Cz + (size_t)r * N + col) =
                make_float2(acc[mf][nf][0], acc[mf][nf][1]);
            *reinterpret_cast<float2*>(Cz + (size_t)(r + 8) * N + col) =
                make_float2(acc[mf][nf][2], acc[mf][nf][3]);
        }
    }
}

// ---------------------------------------------------------------------------
// Conversion kernels
// ---------------------------------------------------------------------------
__global__ void k_split_a(const float* __restrict__ src,
                          __nv_bfloat16* __restrict__ dst, int M)
{
    pdl_wait();
    int i = blockIdx.x * blockDim.x + threadIdx.x;
    int n = M * 512;
    for (; i < n; i += gridDim.x * blockDim.x) {
        int m = i >> 9, j = i & 511;
        __nv_bfloat16 hi, lo;
        split_bf(src[i], hi, lo);
        __nv_bfloat16* d = dst + (size_t)m * KBF;
        d[j] = hi; d[j + 512] = hi; d[j + 1024] = lo;
    }
}

__global__ void k_split_b(const float* __restrict__ src, int ld,
                          __nv_bfloat16* __restrict__ dst, int Nreal, int Npad)
{
    pdl_wait();
    int i = blockIdx.x * blockDim.x + threadIdx.x;
    int n = Npad * 512;
    for (; i < n; i += gridDim.x * blockDim.x) {
        int r = i >> 9, j = i & 511;
        float x = (r < Nreal) ? src[(size_t)r * ld + j] : 0.f;
        __nv_bfloat16 hi, lo;
        split_bf(x, hi, lo);
        __nv_bfloat16* d = dst + (size_t)r * KBF;
        d[j] = hi; d[j + 512] = lo; d[j + 1024] = hi;
    }
}

__global__ void k_split_b16(const float* __restrict__ src, int ld,
                            __half* __restrict__ dst, int Nreal, int Npad)
{
    pdl_wait();
    int i = blockIdx.x * blockDim.x + threadIdx.x;
    int n = Npad * 512;
    for (; i < n; i += gridDim.x * blockDim.x) {
        int r = i >> 9, j = i & 511;
        float x = (r < Nreal) ? src[(size_t)r * ld + j] : 0.f;
        dst[(size_t)r * KH1 + j] = __float2half(x);
    }
}

// ---------------------------------------------------------------------------
// Prep: zero c/slC, fuse biases, build B-side split weights for recurrence
// ---------------------------------------------------------------------------
__global__ void k_prep(const float* __restrict__ b_ih, const float* __restrict__ b_hh,
                       const float* __restrict__ W_attn, const float* __restrict__ W_hh,
                       const float* __restrict__ W_ih, const float* __restrict__ W_attd)
{
    int idx = blockIdx.x * blockDim.x + threadIdx.x;
    int stride = gridDim.x * blockDim.x;
    for (int i = idx; i < B*H; i += stride)
        g_buf[C_OFF + i] = 0.f;
    for (int i = idx; i < 8*B*NC; i += stride)
        g_buf[SLC_OFF + i] = 0.f;
    for (int i = idx; i < G4; i += stride)
        g_buf[BS_OFF + i] = b_ih[i] + b_hh[i];
    for (int i = idx; i < NC*512; i += stride) {
        int r = i >> 9, k = i & 511;
        float x = (r < A) ? W_attn[(size_t)r*(E+H) + E + k]
                          : W_hh[(size_t)(r - A)*H + k];
        __nv_bfloat16 hi, lo;
        split_bf(x, hi, lo);
        __nv_bfloat16* d = g_wcomb_bf + (size_t)r * KBF;
        d[k] = hi; d[k + 512] = lo; d[k + 1024] = hi;
    }
    for (int i = idx; i < G4*512; i += stride) {
        int r = i >> 9, k = i & 511;
        __nv_bfloat16 hi, lo;
        split_bf(W_ih[(size_t)r*E + k], hi, lo);
        __nv_bfloat16* d = g_wih_bf + (size_t)r * KBF;
        d[k] = hi; d[k + 512] = lo; d[k + 1024] = hi;
    }
    for (int i = idx; i < E*2048; i += stride) {
        int r = i >> 11, k = i & 2047;
        __nv_bfloat16 hi, lo;
        split_bf(W_attd[(size_t)r*(E+A) + E + k], hi, lo);
        __nv_bfloat16* d = g_wattd2_bf + (size_t)r * KBFA;
        d[k] = hi; d[k + 2048] = lo; d[k + 4096] = hi;
    }
}

__global__ void k_build_xs(const float* __restrict__ features,
                           const int*   __restrict__ captions,
                           const float* __restrict__ embed)
{
    pdl_wait();
    int idx = blockIdx.x * blockDim.x + threadIdx.x;
    int stride = gridDim.x * blockDim.x;
    for (int i = idx; i < TP1*B*E; i += stride) {
        int e  = i & (E - 1);
        int be = i >> 9;
        int b  = be & (B - 1);
        int t  = be >> 7;
        float v;
        if (t == 0) {
            v = features[b*E + e];
        } else {
            int tok = captions[b*T + (t - 1)];
            v = embed[(size_t)tok*E + e];
        }
        g_buf[XS_OFF + i] = v;
    }
}

// ---------------------------------------------------------------------------
// softmax(pan[t] + 8 comb slabs cols[0:A]) * cnn -> att_bf (split A-side)
// ---------------------------------------------------------------------------
__global__ void __launch_bounds__(256)
k_softmax_att(const float* __restrict__ pre,
              const float* __restrict__ slc,
              const float* __restrict__ cnn)
{
    pdl_wait();
    int b = blockIdx.x;
    int t = threadIdx.x;
    const size_t o0 = (size_t)b*A;
    const float* s0 = slc + (size_t)b*NC;
    const size_t SS = (size_t)B*NC;
    float v[8];
    float mx = -1e30f;
#pragma unroll
    for (int i = 0; i < 8; ++i) {
        int j = t + 256*i;
        float s = pre[o0 + j];
#pragma unroll
        for (int z = 0; z < 8; ++z) s += s0[j + (size_t)z*SS];
        v[i] = s;
        mx = fmaxf(mx, s);
    }
    __shared__ float red[256];
    red[t] = mx; __syncthreads();
    for (int off = 128; off > 0; off >>= 1) {
        if (t < off) red[t] = fmaxf(red[t], red[t + off]);
        __syncthreads();
    }
    mx = red[0]; __syncthreads();

    float sum = 0.f;
#pragma unroll
    for (int i = 0; i < 8; ++i) {
        v[i] = expf(v[i] - mx);
        sum += v[i];
    }
    red[t] = sum; __syncthreads();
    for (int off = 128; off > 0; off >>= 1) {
        if (t < off) red[t] += red[t + off];
        __syncthreads();
    }
    float inv = 1.f / red[0];

    const float* cb = cnn + o0;
    __nv_bfloat16* ab = g_att_bf + (size_t)b * KBFA;
#pragma unroll
    for (int i = 0; i < 8; ++i) {
        int j = t + 256*i;
        float x = cb[j] * v[i] * inv;
        __nv_bfloat16 hi, lo;
        split_bf(x, hi, lo);
        ab[j] = hi; ab[j + 2048] = hi; ab[j + 4096] = lo;
    }
}

// x2 = pad[t] + sum of 32 slD slabs -> x2_bf (split A-side)
__global__ void __launch_bounds__(256)
k_reduce_attd(const float* __restrict__ pre,
              const float* __restrict__ slab)
{
    pdl_wait();
    int i = blockIdx.x * blockDim.x + threadIdx.x;
    if (i >= B*E) return;
    float s = pre[i];
#pragma unroll
    for (int z = 0; z < 32; ++z) s += slab[i + (size_t)z*B*E];
    int b = i >> 9, j = i & 511;
    __nv_bfloat16 hi, lo;
    split_bf(s, hi, lo);
    __nv_bfloat16* d = g_x2_bf + (size_t)b * KBF;
    d[j] = hi; d[j + 512] = hi; d[j + 1024] = lo;
}

// LSTM pointwise: gates = bsum + 8 comb slabs (cols A..) + 8 gate_x slabs.
__global__ void __launch_bounds__(256)
k_lstm_red(const float* __restrict__ slc,
           const float* __restrict__ slg,
           const float* __restrict__ bsum,
           float* __restrict__ c,
           __half* __restrict__ hid16)
{
    pdl_wait();
    int idx = blockIdx.x * blockDim.x + threadIdx.x;
    if (idx >= B*H) return;
    int b = idx >> 9;
    int j = idx & 511;
    float gi = bsum[j], gf = bsum[j + 512], gg = bsum[j + 1024], go = bsum[j + 1536];
#pragma unroll
    for (int z = 0; z < 8; ++z) {
        const float* gc = slc + (size_t)z*B*NC + (size_t)b*NC + A;
        gi += gc[j];  gf += gc[j + 512];
        gg += gc[j + 1024];  go += gc[j + 1536];
    }
#pragma unroll
    for (int z = 0; z < 8; ++z) {
        const float* gx = slg + (size_t)z*B*G4 + (size_t)b*G4;
        gi += gx[j];  gf += gx[j + 512];
        gg += gx[j + 1024];  go += gx[j + 1536];
    }
    float ig = 1.f / (1.f + expf(-gi));
    float fg = 1.f / (1.f + expf(-gf));
    float gt = tanhf(gg);
    float og = 1.f / (1.f + expf(-go));
    float cn = fg * c[idx] + ig * gt;
    float hn = og * tanhf(cn);
    c[idx] = cn;
    __nv_bfloat16 hi, lo;
    split_bf(hn, hi, lo);
    __nv_bfloat16* d = g_h_bf + (size_t)b * KBF;
    d[j] = hi; d[j + 512] = hi; d[j + 1024] = lo;
    hid16[(size_t)b * KH1 + j] = __float2half(hn);
}

// ---------------------------------------------------------------------------
// Host: PDL launch helper
// ---------------------------------------------------------------------------
template<typename F, typename... Args>
static inline void pdl_launch(F func, dim3 gd, dim3 bd, size_t sh, Args... args)
{
    cudaLaunchConfig_t cfg = {};
    cfg.gridDim = gd;
    cfg.blockDim = bd;
    cfg.dynamicSmemBytes = sh;
    cudaLaunchAttribute attr[1];
    attr[0].id = cudaLaunchAttributeProgrammaticStreamSerialization;
    attr[0].val.programmaticStreamSerializationAllowed = 1;
    cfg.attrs = attr;
    cfg.numAttrs = 1;
    cudaLaunchKernelEx(&cfg, func, args...);
}

// ---------------------------------------------------------------------------
// Host launch sequence (graph-capturable: kernel launches only)
// ---------------------------------------------------------------------------
extern "C" void kernel_launch(void* const* d_in, const int* in_sizes, int n_in,
                              void* d_out, int out_size)
{
    const float* features = (const float*)d_in[0];
    const float* cnn      = (const float*)d_in[1];
    const int*   captions = (const int*)  d_in[2];
    /* d_in[3] = lengths (unused: all T+1) */
    const float* embed    = (const float*)d_in[4];
    const float* W_ih     = (const float*)d_in[5];
    const float* W_hh     = (const float*)d_in[6];
    const float* b_ih     = (const float*)d_in[7];
    const float* b_hh     = (const float*)d_in[8];
    const float* W_attn   = (const float*)d_in[9];
    const float* b_attn   = (const float*)d_in[10];
    const float* W_attd   = (const float*)d_in[11];
    const float* b_attd   = (const float*)d_in[12];
    const float* W_out    = (const float*)d_in[13];
    const float* b_out    = (const float*)d_in[14];
    float* out = (float*)d_out;

    float* buf = nullptr;
    cudaGetSymbolAddress((void**)&buf, g_buf);
    __nv_bfloat16 *xs_bf, *wattn_bf, *wattd_bf, *h_bf, *x2_bf, *att_bf;
    __nv_bfloat16 *wcomb_bf, *wih_bf, *wattd2_bf;
    __half *hid_h, *wout_h;
    cudaGetSymbolAddress((void**)&xs_bf,     g_xs_bf);
    cudaGetSymbolAddress((void**)&wattn_bf,  g_wattn_bf);
    cudaGetSymbolAddress((void**)&wattd_bf,  g_wattd_bf);
    cudaGetSymbolAddress((void**)&h_bf,      g_h_bf);
    cudaGetSymbolAddress((void**)&att_bf,    g_att_bf);
    cudaGetSymbolAddress((void**)&x2_bf,     g_x2_bf);
    cudaGetSymbolAddress((void**)&wcomb_bf,  g_wcomb_bf);
    cudaGetSymbolAddress((void**)&wih_bf,    g_wih_bf);
    cudaGetSymbolAddress((void**)&wattd2_bf, g_wattd2_bf);
    cudaGetSymbolAddress((void**)&hid_h,     g_hid_h);
    cudaGetSymbolAddress((void**)&wout_h,    g_wout_h);

    cudaFuncSetAttribute(hmma_gemm<KBF, false>,
                         cudaFuncAttributeMaxDynamicSharedMemorySize, HSMEM);
    cudaFuncSetAttribute(hmma_gemm2<KBF, false>,
                         cudaFuncAttributeMaxDynamicSharedMemorySize, HSMEM2);
    cudaFuncSetAttribute(hmma_gemm2<KH1, true>,
                         cudaFuncAttributeMaxDynamicSharedMemorySize, HSMEM2);
    cudaFuncSetAttribute(hmma_rec,
                         cudaFuncAttributeMaxDynamicSharedMemorySize, HSMEM);

    float* xs   = buf + XS_OFF;
    float* pan  = buf + PAN_OFF;
    float* pad  = buf + PAD_OFF;
    float* cbuf = buf + C_OFF;
    float* slC  = buf + SLC_OFF;
    float* slD  = buf + SLD_OFF;
    float* slG  = buf + SLG_OFF;
    float* bsum = buf + BS_OFF;

    // prep
    pdl_launch(k_prep, dim3(2048), dim3(256), 0,
               b_ih, b_hh, W_attn, W_hh, W_ih, W_attd);
    pdl_launch(k_build_xs, dim3(2048), dim3(256), 0, features, captions, embed);

    // conversions
    pdl_launch(k_split_a, dim3(4096), dim3(256), 0,
               (const float*)xs, xs_bf, (int)MALL);
    pdl_launch(k_split_b, dim3(2048), dim3(256), 0,
               W_attn, (int)(E + H), wattn_bf, (int)A, (int)A);
    pdl_launch(k_split_b, dim3(1024), dim3(256), 0,
               W_attd, (int)(E + A), wattd_bf, (int)E, (int)E);
    pdl_launch(k_split_b16, dim3(4096), dim3(256), 0,
               W_out, (int)H, wout_h, (int)V, (int)VPAD);

    // pan[t] = x_t @ W_attn[:, :E]^T + b_attn  (bf16 3-term, 128x256 tile)
    pdl_launch(hmma_gemm2<KBF, false>, dim3(A / 256, MALL / 128), dim3(256),
               (size_t)HSMEM2, pan, (int)A, (int)A,
               (const uint16_t*)xs_bf, (const uint16_t*)wattn_bf, b_attn);
    // pad[t] = x_t @ W_attd[:, :E]^T + b_attd  (bf16 3-term, 128x128 tile)
    pdl_launch(hmma_gemm<KBF, false>, dim3(E / 128, MALL / 128), dim3(256),
               (size_t)HSMEM, pad, (int)E, (int)E,
               (const uint16_t*)xs_bf, (const uint16_t*)wattd_bf, b_attd);

    const int NLSTM = (B*H + 255)/256;

    // t = 0: gate_x = xs0 @ W_ih^T (xs_bf rows 0..127); comb slabs zeroed
    pdl_launch(hmma_rec, dim3(G4/128, 1, 8), dim3(256), (size_t)HSMEM,
               slG, (int)G4, (const uint16_t*)xs_bf,
               (const uint16_t*)wih_bf, (int)KBF, (int)(KBF/8));
    pdl_launch(k_lstm_red, dim3(NLSTM), dim3(256), 0,
               (const float*)slC, (const float*)slG, (const float*)bsum,
               cbuf, hid_h);

    // t = 1..T
    for (int t = 1; t <= T; ++t) {
        // comb: [scores | gates_h] = h @ Wcomb^T  (splitK8 -> 256 blocks)
        pdl_launch(hmma_rec, dim3(NC/128, 1, 8), dim3(256), (size_t)HSMEM,
                   slC, (int)NC, (const uint16_t*)h_bf,
                   (const uint16_t*)wcomb_bf, (int)KBF, (int)(KBF/8));

        // softmax(pan[t] + slabs) * cnn -> att_bf
        pdl_launch(k_softmax_att, dim3(B), dim3(256), 0,
                   (const float*)(pan + (size_t)t*B*A), (const float*)slC, cnn);

        // attd: slD[z] = att @ W_attd[:, E:]^T  (splitK32 -> 128 blocks)
        pdl_launch(hmma_rec, dim3(E/128, 1, 32), dim3(256), (size_t)HSMEM,
                   slD, (int)E, (const uint16_t*)att_bf,
                   (const uint16_t*)wattd2_bf, (int)KBFA, (int)(KBFA/32));

        // x2 = pad[t] + sum slD -> x2_bf
        pdl_launch(k_reduce_attd, dim3((B*E + 255)/256), dim3(256), 0,
                   (const float*)(pad + (size_t)t*B*E), (const float*)slD);

        // gate_x: slG = x2 @ W_ih^T  (splitK8 -> 128 blocks)
        pdl_launch(hmma_rec, dim3(G4/128, 1, 8), dim3(256), (size_t)HSMEM,
                   slG, (int)G4, (const uint16_t*)x2_bf,
                   (const uint16_t*)wih_bf, (int)KBF, (int)(KBF/8));

        // LSTM pointwise; h -> split-bf16 + fp16 row t
        pdl_launch(k_lstm_red, dim3(NLSTM), dim3(256), 0,
                   (const float*)slC, (const float*)slG, (const float*)bsum,
                   cbuf, hid_h + (size_t)t*B*KH1);
    }

    // logits = hidden @ W_out^T + b_out  (fp16 1-term, 128x256 tile)
    pdl_launch(hmma_gemm2<KH1, true>, dim3(VPAD / 256, MALL / 128), dim3(256),
               (size_t)HSMEM2, out, (int)V, (int)V,
               (const uint16_t*)hid_h, (const uint16_t*)wout_h, b_out);
}

// round 12
// speedup vs baseline: 1.0910x; 1.0910x over previous
#include <cuda_runtime.h>
#include <cuda_bf16.h>
#include <cuda_fp16.h>
#include <math.h>
#include <stdint.h>
#include <utility>

// ---------------------------------------------------------------------------
// Problem constants
// ---------------------------------------------------------------------------
namespace {
constexpr int B   = 128;
constexpr int T   = 31;
constexpr int TP1 = 32;     // T+1
constexpr int E   = 512;
constexpr int H   = 512;
constexpr int V   = 10000;
constexpr int A   = 2048;
constexpr int G4  = 2048;   // 4*H
constexpr int NC  = 4096;   // comb cols: [scores | gates_h]
constexpr int MALL = TP1 * B;   // 4096
constexpr int VPAD = 10240;     // 80 * 128
constexpr int KBF  = 1536;      // 3 * 512 split-bf16 K
constexpr int KBFA = 6144;      // 3 * 2048 split-bf16 K (attd)
constexpr int KH1  = 512;       // 1-term fp16 K (logits)

// fp32 scratch layout (fp32 xs eliminated — split-bf16 built directly)
constexpr size_t PAN_OFF  = 0;                              // [TP1][B][A]
constexpr size_t PAD_OFF  = PAN_OFF + (size_t)TP1*B*A;      // [TP1][B][E]
constexpr size_t C_OFF    = PAD_OFF + (size_t)TP1*B*E;      // [B][H]
constexpr size_t SLC_OFF  = C_OFF   + (size_t)B*H;          // [4][B][NC]
constexpr size_t SLD_OFF  = SLC_OFF + (size_t)4*B*NC;       // [32][B][E]
constexpr size_t SLG_OFF  = SLD_OFF + (size_t)32*B*E;       // [8][B][G4]
constexpr size_t BS_OFF   = SLG_OFF + (size_t)8*B*G4;       // [G4]
constexpr size_t BUF_TOTAL = BS_OFF + (size_t)G4;
}

__device__ float g_buf[BUF_TOTAL];

// bf16 split operand buffers
__device__ __nv_bfloat16 g_xs_bf   [(size_t)MALL * KBF];   // A-side [hi|hi|lo]
__device__ __nv_bfloat16 g_wattn_bf[(size_t)A * KBF];      // B-side (pan)
__device__ __nv_bfloat16 g_wattd_bf[(size_t)E * KBF];      // B-side (pad)
__device__ __nv_bfloat16 g_h_bf    [(size_t)B * KBF];      // A-side h
__device__ __nv_bfloat16 g_att_bf  [(size_t)B * KBFA];     // A-side att
__device__ __nv_bfloat16 g_x2_bf   [(size_t)B * KBF];      // A-side x2
__device__ __nv_bfloat16 g_wcomb_bf[(size_t)NC * KBF];     // B-side comb W
__device__ __nv_bfloat16 g_wih_bf  [(size_t)G4 * KBF];     // B-side W_ih
__device__ __nv_bfloat16 g_wattd2_bf[(size_t)E * KBFA];    // B-side W_attd[:,E:]
// fp16 1-term buffers (logits)
__device__ __half g_hid_h [(size_t)MALL * KH1];
__device__ __half g_wout_h[(size_t)VPAD * KH1];

__device__ __forceinline__ void pdl_wait() {
    asm volatile("griddepcontrol.wait;" ::: "memory");
}

__device__ __forceinline__ void split_bf(float x, __nv_bfloat16& hi, __nv_bfloat16& lo) {
    hi = __float2bfloat16(x);
    lo = __float2bfloat16(x - __bfloat162float(hi));
}

// ---------------------------------------------------------------------------
// HMMA helpers (sm_80+ PTX)
// ---------------------------------------------------------------------------
__device__ __forceinline__ uint32_t smem_u32(const void* p) {
    uint32_t a;
    asm("{ .reg .u64 t; cvta.to.shared.u64 t, %1; cvt.u32.u64 %0, t; }"
        : "=r"(a) : "l"(p));
    return a;
}
__device__ __forceinline__ void cpa16(uint32_t s, const void* g) {
    asm volatile("cp.async.cg.shared.global [%0], [%1], 16;"
                 :: "r"(s), "l"(g));
}
#define CP_COMMIT() asm volatile("cp.async.commit_group;" ::: "memory")
#define CP_WAIT(N)  asm volatile("cp.async.wait_group %0;" :: "n"(N) : "memory")

#define LDSM4(R0, R1, R2, R3, ADDR) \
    asm volatile("ldmatrix.sync.aligned.m8n8.x4.shared.b16 {%0,%1,%2,%3}, [%4];" \
        : "=r"(R0), "=r"(R1), "=r"(R2), "=r"(R3) : "r"(ADDR))

template<bool FP16>
__device__ __forceinline__ void mma16816(float* d, const uint32_t* a,
                                         uint32_t b0, uint32_t b1) {
    if constexpr (FP16) {
        asm volatile(
            "mma.sync.aligned.m16n8k16.row.col.f32.f16.f16.f32 "
            "{%0,%1,%2,%3}, {%4,%5,%6,%7}, {%8,%9}, {%0,%1,%2,%3};"
            : "+f"(d[0]), "+f"(d[1]), "+f"(d[2]), "+f"(d[3])
            : "r"(a[0]), "r"(a[1]), "r"(a[2]), "r"(a[3]), "r"(b0), "r"(b1));
    } else {
        asm volatile(
            "mma.sync.aligned.m16n8k16.row.col.f32.bf16.bf16.f32 "
            "{%0,%1,%2,%3}, {%4,%5,%6,%7}, {%8,%9}, {%0,%1,%2,%3};"
            : "+f"(d[0]), "+f"(d[1]), "+f"(d[2]), "+f"(d[3])
            : "r"(a[0]), "r"(a[1]), "r"(a[2]), "r"(a[3]), "r"(b0), "r"(b1));
    }
}

namespace {
constexpr int HBK   = 32;
constexpr int HROWB = 80;            // 32 elems * 2B + 16B pad
constexpr int HSTG  = 256 * HROWB;   // 20480 B per stage
constexpr int HSMEM = 3 * HSTG;      // 61440 B
}

// ---------------------------------------------------------------------------
// hmma_gemm: big parallel GEMMs (pan/pad/logits). 128x128, 2 CTA/SM.
// ---------------------------------------------------------------------------
template<int KTOT, bool FP16>
__global__ void __launch_bounds__(256, 2)
hmma_gemm(float* __restrict__ C, int ldc, int Nreal,
          const uint16_t* __restrict__ Abf,
          const uint16_t* __restrict__ Bbf,
          const float* __restrict__ bias)
{
    pdl_wait();
    constexpr int NT = KTOT / HBK;
    extern __shared__ __align__(16) char sm[];
    const uint32_t sb = smem_u32(sm);

    const int tid  = threadIdx.x;
    const int wid  = tid >> 5;
    const int lane = tid & 31;
    const int wm   = wid & 1;
    const int wn   = wid >> 1;
    const int row0 = blockIdx.y * 128;
    const int col0 = blockIdx.x * 128;

    const int qr0 = (tid)       >> 2, qc0 = (tid)       & 3;
    const int qr1 = (tid + 256) >> 2, qc1 = (tid + 256) & 3;

    auto LOADG = [&](int t, int stg) {
        const int k0 = t * HBK;
        const uint32_t sa  = sb + stg * HSTG;
        const uint32_t sbm = sa + 128 * HROWB;
        cpa16(sa  + qr0 * HROWB + qc0 * 16,
              Abf + (size_t)(row0 + qr0) * KTOT + k0 + qc0 * 8);
        cpa16(sa  + qr1 * HROWB + qc1 * 16,
              Abf + (size_t)(row0 + qr1) * KTOT + k0 + qc1 * 8);
        cpa16(sbm + qr0 * HROWB + qc0 * 16,
              Bbf + (size_t)(col0 + qr0) * KTOT + k0 + qc0 * 8);
        cpa16(sbm + qr1 * HROWB + qc1 * 16,
              Bbf + (size_t)(col0 + qr1) * KTOT + k0 + qc1 * 8);
    };

    float acc[4][4][4];
#pragma unroll
    for (int i = 0; i < 4; ++i)
#pragma unroll
        for (int j = 0; j < 4; ++j)
#pragma unroll
            for (int q = 0; q < 4; ++q) acc[i][j][q] = 0.f;

    const int lr  = lane & 15;
    const int lkb = (lane >> 4) * 16;

    LOADG(0, 0); CP_COMMIT();
    LOADG(1, 1); CP_COMMIT();

    for (int t = 0; t < NT; ++t) {
        if (t + 1 < NT) { CP_WAIT(1); } else { CP_WAIT(0); }
        __syncthreads();
        if (t + 2 < NT) { LOADG(t + 2, (t + 2) % 3); CP_COMMIT(); }

        const uint32_t aB = sb + (t % 3) * HSTG;
        const uint32_t bB = aB + 128 * HROWB;
#pragma unroll
        for (int ks = 0; ks < 2; ++ks) {
            const int kbyte = ks * 32 + lkb;
            uint32_t af[4][4];
#pragma unroll
            for (int mf = 0; mf < 4; ++mf)
                LDSM4(af[mf][0], af[mf][1], af[mf][2], af[mf][3],
                      aB + (wm * 64 + mf * 16 + lr) * HROWB + kbyte);
            uint32_t bfr[2][4];
#pragma unroll
            for (int p = 0; p < 2; ++p)
                LDSM4(bfr[p][0], bfr[p][1], bfr[p][2], bfr[p][3],
                      bB + (wn * 32 + p * 16 + lr) * HROWB + kbyte);
#pragma unroll
            for (int mf = 0; mf < 4; ++mf)
#pragma unroll
                for (int nf = 0; nf < 4; ++nf)
                    mma16816<FP16>(acc[mf][nf], af[mf],
                                   bfr[nf >> 1][nf & 1], bfr[nf >> 1][(nf & 1) + 2]);
        }
    }

    const int rbase = row0 + wm * 64 + (lane >> 2);
    const int cbase = col0 + wn * 32 + 2 * (lane & 3);
#pragma unroll
    for (int nf = 0; nf < 4; ++nf) {
        const int col = cbase + nf * 8;
        if (col >= Nreal) continue;
        const float2 bv = *reinterpret_cast<const float2*>(bias + col);
#pragma unroll
        for (int mf = 0; mf < 4; ++mf) {
            const int r = rbase + mf * 16;
            *reinterpret_cast<float2*>(C + (size_t)r * ldc + col) =
                make_float2(acc[mf][nf][0] + bv.x, acc[mf][nf][1] + bv.y);
            *reinterpret_cast<float2*>(C + (size_t)(r + 8) * ldc + col) =
                make_float2(acc[mf][nf][2] + bv.x, acc[mf][nf][3] + bv.y);
        }
    }
}

// ---------------------------------------------------------------------------
// hmma_rec: recurrent-step GEMM. M = 128, runtime K range, split-K slabs.
// ---------------------------------------------------------------------------
__global__ void __launch_bounds__(256, 2)
hmma_rec(float* __restrict__ C, int N,
         const uint16_t* __restrict__ Abf,
         const uint16_t* __restrict__ Bbf, int lda,
         int KC)
{
    pdl_wait();
    extern __shared__ __align__(16) char sm[];
    const uint32_t sb = smem_u32(sm);

    const int NT   = KC / HBK;
    const int kbeg = blockIdx.z * KC;
    const int tid  = threadIdx.x;
    const int wid  = tid >> 5;
    const int lane = tid & 31;
    const int wm   = wid & 1;
    const int wn   = wid >> 1;
    const int col0 = blockIdx.x * 128;
    float* Cz = C + (size_t)blockIdx.z * 128 * N;

    const int qr0 = (tid)       >> 2, qc0 = (tid)       & 3;
    const int qr1 = (tid + 256) >> 2, qc1 = (tid + 256) & 3;

    auto LOADG = [&](int t, int stg) {
        const int k0 = kbeg + t * HBK;
        const uint32_t sa  = sb + stg * HSTG;
        const uint32_t sbm = sa + 128 * HROWB;
        cpa16(sa  + qr0 * HROWB + qc0 * 16,
              Abf + (size_t)qr0 * lda + k0 + qc0 * 8);
        cpa16(sa  + qr1 * HROWB + qc1 * 16,
              Abf + (size_t)qr1 * lda + k0 + qc1 * 8);
        cpa16(sbm + qr0 * HROWB + qc0 * 16,
              Bbf + (size_t)(col0 + qr0) * lda + k0 + qc0 * 8);
        cpa16(sbm + qr1 * HROWB + qc1 * 16,
              Bbf + (size_t)(col0 + qr1) * lda + k0 + qc1 * 8);
    };

    float acc[4][4][4];
#pragma unroll
    for (int i = 0; i < 4; ++i)
#pragma unroll
        for (int j = 0; j < 4; ++j)
#pragma unroll
            for (int q = 0; q < 4; ++q) acc[i][j][q] = 0.f;

    const int lr  = lane & 15;
    const int lkb = (lane >> 4) * 16;

    LOADG(0, 0); CP_COMMIT();
    LOADG(1, 1); CP_COMMIT();

    for (int t = 0; t < NT; ++t) {
        if (t + 1 < NT) { CP_WAIT(1); } else { CP_WAIT(0); }
        __syncthreads();
        if (t + 2 < NT) { LOADG(t + 2, (t + 2) % 3); CP_COMMIT(); }

        const uint32_t aB = sb + (t % 3) * HSTG;
        const uint32_t bB = aB + 128 * HROWB;
#pragma unroll
        for (int ks = 0; ks < 2; ++ks) {
            const int kbyte = ks * 32 + lkb;
            uint32_t af[4][4];
#pragma unroll
            for (int mf = 0; mf < 4; ++mf)
                LDSM4(af[mf][0], af[mf][1], af[mf][2], af[mf][3],
                      aB + (wm * 64 + mf * 16 + lr) * HROWB + kbyte);
            uint32_t bfr[2][4];
#pragma unroll
            for (int p = 0; p < 2; ++p)
                LDSM4(bfr[p][0], bfr[p][1], bfr[p][2], bfr[p][3],
                      bB + (wn * 32 + p * 16 + lr) * HROWB + kbyte);
#pragma unroll
            for (int mf = 0; mf < 4; ++mf)
#pragma unroll
                for (int nf = 0; nf < 4; ++nf)
                    mma16816<false>(acc[mf][nf], af[mf],
                                    bfr[nf >> 1][nf & 1], bfr[nf >> 1][(nf & 1) + 2]);
        }
    }

    const int rbase = wm * 64 + (lane >> 2);
    const int cbase = col0 + wn * 32 + 2 * (lane & 3);
#pragma unroll
    for (int nf = 0; nf < 4; ++nf) {
        const int col = cbase + nf * 8;
#pragma unroll
        for (int mf = 0; mf < 4; ++mf) {
            const int r = rbase + mf * 16;
            *reinterpret_cast<float2*>(Cz + (size_t)r * N + col) =
                make_float2(acc[mf][nf][0], acc[mf][nf][1]);
            *reinterpret_cast<float2*>(Cz + (size_t)(r + 8) * N + col) =
                make_float2(acc[mf][nf][2], acc[mf][nf][3]);
        }
    }
}

// ---------------------------------------------------------------------------
// Conversion kernels
// ---------------------------------------------------------------------------
// Fused xs build + split: xs[0]=features, xs[t]=embed[captions[:,t-1]], written
// directly as A-side split-bf16 [hi|hi|lo]. fp32 xs never materialized.
__global__ void k_build_xs_bf(const float* __restrict__ features,
                              const int*   __restrict__ captions,
                              const float* __restrict__ embed)
{
    pdl_wait();
    int idx = blockIdx.x * blockDim.x + threadIdx.x;
    int stride = gridDim.x * blockDim.x;
    for (int i = idx; i < TP1*B*E; i += stride) {
        int e  = i & (E - 1);
        int be = i >> 9;
        int b  = be & (B - 1);
        int t  = be >> 7;
        float v;
        if (t == 0) {
            v = features[b*E + e];
        } else {
            int tok = captions[b*T + (t - 1)];
            v = embed[(size_t)tok*E + e];
        }
        __nv_bfloat16 hi, lo;
        split_bf(v, hi, lo);
        __nv_bfloat16* d = g_xs_bf + (size_t)(t * B + b) * KBF;
        d[e] = hi; d[e + 512] = hi; d[e + 1024] = lo;
    }
}

// B-side 3-term: [hi | lo | hi], Korig=512
__global__ void k_split_b(const float* __restrict__ src, int ld,
                          __nv_bfloat16* __restrict__ dst, int Nreal, int Npad)
{
    pdl_wait();
    int i = blockIdx.x * blockDim.x + threadIdx.x;
    int n = Npad * 512;
    for (; i < n; i += gridDim.x * blockDim.x) {
        int r = i >> 9, j = i & 511;
        float x = (r < Nreal) ? src[(size_t)r * ld + j] : 0.f;
        __nv_bfloat16 hi, lo;
        split_bf(x, hi, lo);
        __nv_bfloat16* d = dst + (size_t)r * KBF;
        d[j] = hi; d[j + 512] = lo; d[j + 1024] = hi;
    }
}

// fp16 1-term (W_out)
__global__ void k_split_b16(const float* __restrict__ src, int ld,
                            __half* __restrict__ dst, int Nreal, int Npad)
{
    pdl_wait();
    int i = blockIdx.x * blockDim.x + threadIdx.x;
    int n = Npad * 512;
    for (; i < n; i += gridDim.x * blockDim.x) {
        int r = i >> 9, j = i & 511;
        float x = (r < Nreal) ? src[(size_t)r * ld + j] : 0.f;
        dst[(size_t)r * KH1 + j] = __float2half(x);
    }
}

// ---------------------------------------------------------------------------
// Prep: zero c, fuse biases, build B-side split weights (no slab zero-fill)
// ---------------------------------------------------------------------------
__global__ void k_prep(const float* __restrict__ b_ih, const float* __restrict__ b_hh,
                       const float* __restrict__ W_attn, const float* __restrict__ W_hh,
                       const float* __restrict__ W_ih, const float* __restrict__ W_attd)
{
    int idx = blockIdx.x * blockDim.x + threadIdx.x;
    int stride = gridDim.x * blockDim.x;
    for (int i = idx; i < B*H; i += stride)
        g_buf[C_OFF + i] = 0.f;
    for (int i = idx; i < G4; i += stride)
        g_buf[BS_OFF + i] = b_ih[i] + b_hh[i];
    // Wcomb_bf [4096][1536]: rows 0..2047 = W_attn[:, E:], rows 2048.. = W_hh
    for (int i = idx; i < NC*512; i += stride) {
        int r = i >> 9, k = i & 511;
        float x = (r < A) ? W_attn[(size_t)r*(E+H) + E + k]
                          : W_hh[(size_t)(r - A)*H + k];
        __nv_bfloat16 hi, lo;
        split_bf(x, hi, lo);
        __nv_bfloat16* d = g_wcomb_bf + (size_t)r * KBF;
        d[k] = hi; d[k + 512] = lo; d[k + 1024] = hi;
    }
    // Wih_bf [2048][1536]
    for (int i = idx; i < G4*512; i += stride) {
        int r = i >> 9, k = i & 511;
        __nv_bfloat16 hi, lo;
        split_bf(W_ih[(size_t)r*E + k], hi, lo);
        __nv_bfloat16* d = g_wih_bf + (size_t)r * KBF;
        d[k] = hi; d[k + 512] = lo; d[k + 1024] = hi;
    }
    // Wattd2_bf [512][6144] from W_attd[:, E:] (Korig = 2048)
    for (int i = idx; i < E*2048; i += stride) {
        int r = i >> 11, k = i & 2047;
        __nv_bfloat16 hi, lo;
        split_bf(W_attd[(size_t)r*(E+A) + E + k], hi, lo);
        __nv_bfloat16* d = g_wattd2_bf + (size_t)r * KBFA;
        d[k] = hi; d[k + 2048] = lo; d[k + 4096] = hi;
    }
}

// ---------------------------------------------------------------------------
// softmax(pan[t] + 4 comb slabs cols[0:A]) * cnn -> att_bf (split A-side)
// ---------------------------------------------------------------------------
__global__ void __launch_bounds__(256)
k_softmax_att(const float* __restrict__ pre,
              const float* __restrict__ slc,
              const float* __restrict__ cnn)
{
    pdl_wait();
    int b = blockIdx.x;
    int t = threadIdx.x;
    const size_t o0 = (size_t)b*A;
    const float* s0 = slc + (size_t)b*NC;
    const size_t SS = (size_t)B*NC;
    float v[8];
    float mx = -1e30f;
#pragma unroll
    for (int i = 0; i < 8; ++i) {
        int j = t + 256*i;
        float s = pre[o0 + j] + s0[j] + s0[j + SS] + s0[j + 2*SS] + s0[j + 3*SS];
        v[i] = s;
        mx = fmaxf(mx, s);
    }
    __shared__ float red[256];
    red[t] = mx; __syncthreads();
    for (int off = 128; off > 0; off >>= 1) {
        if (t < off) red[t] = fmaxf(red[t], red[t + off]);
        __syncthreads();
    }
    mx = red[0]; __syncthreads();

    float sum = 0.f;
#pragma unroll
    for (int i = 0; i < 8; ++i) {
        v[i] = expf(v[i] - mx);
        sum += v[i];
    }
    red[t] = sum; __syncthreads();
    for (int off = 128; off > 0; off >>= 1) {
        if (t < off) red[t] += red[t + off];
        __syncthreads();
    }
    float inv = 1.f / red[0];

    const float* cb = cnn + o0;
    __nv_bfloat16* ab = g_att_bf + (size_t)b * KBFA;
#pragma unroll
    for (int i = 0; i < 8; ++i) {
        int j = t + 256*i;
        float x = cb[j] * v[i] * inv;
        __nv_bfloat16 hi, lo;
        split_bf(x, hi, lo);
        ab[j] = hi; ab[j + 2048] = hi; ab[j + 4096] = lo;
    }
}

// x2 = pad[t] + sum of 32 slD slabs -> x2_bf (split A-side)
__global__ void __launch_bounds__(256)
k_reduce_attd(const float* __restrict__ pre,
              const float* __restrict__ slab)
{
    pdl_wait();
    int i = blockIdx.x * blockDim.x + threadIdx.x;
    if (i >= B*E) return;
    float s = pre[i];
#pragma unroll
    for (int z = 0; z < 32; ++z) s += slab[i + (size_t)z*B*E];
    int b = i >> 9, j = i & 511;
    __nv_bfloat16 hi, lo;
    split_bf(s, hi, lo);
    __nv_bfloat16* d = g_x2_bf + (size_t)b * KBF;
    d[j] = hi; d[j + 512] = hi; d[j + 1024] = lo;
}

// LSTM pointwise: gates = bsum + ncomb comb slabs (cols A..) + 8 gate_x slabs.
// ncomb = 0 at t=0 (comb never ran), 4 otherwise.
__global__ void __launch_bounds__(256)
k_lstm_red(const float* __restrict__ slc,
           const float* __restrict__ slg,
           const float* __restrict__ bsum,
           float* __restrict__ c,
           __half* __restrict__ hid16,
           int ncomb)
{
    pdl_wait();
    int idx = blockIdx.x * blockDim.x + threadIdx.x;
    if (idx >= B*H) return;
    int b = idx >> 9;
    int j = idx & 511;
    float gi = bsum[j], gf = bsum[j + 512], gg = bsum[j + 1024], go = bsum[j + 1536];
    for (int z = 0; z < ncomb; ++z) {
        const float* gc = slc + (size_t)z*B*NC + (size_t)b*NC + A;
        gi += gc[j];  gf += gc[j + 512];
        gg += gc[j + 1024];  go += gc[j + 1536];
    }
#pragma unroll
    for (int z = 0; z < 8; ++z) {
        const float* gx = slg + (size_t)z*B*G4 + (size_t)b*G4;
        gi += gx[j];  gf += gx[j + 512];
        gg += gx[j + 1024];  go += gx[j + 1536];
    }
    float ig = 1.f / (1.f + expf(-gi));
    float fg = 1.f / (1.f + expf(-gf));
    float gt = tanhf(gg);
    float og = 1.f / (1.f + expf(-go));
    float cn = fg * c[idx] + ig * gt;
    float hn = og * tanhf(cn);
    c[idx] = cn;
    __nv_bfloat16 hi, lo;
    split_bf(hn, hi, lo);
    __nv_bfloat16* d = g_h_bf + (size_t)b * KBF;
    d[j] = hi; d[j + 512] = hi; d[j + 1024] = lo;
    hid16[(size_t)b * KH1 + j] = __float2half(hn);
}

// ---------------------------------------------------------------------------
// Host: PDL launch helper
// ---------------------------------------------------------------------------
template<typename F, typename... Args>
static inline void pdl_launch(F func, dim3 gd, dim3 bd, size_t sh, Args... args)
{
    cudaLaunchConfig_t cfg = {};
    cfg.gridDim = gd;
    cfg.blockDim = bd;
    cfg.dynamicSmemBytes = sh;
    cudaLaunchAttribute attr[1];
    attr[0].id = cudaLaunchAttributeProgrammaticStreamSerialization;
    attr[0].val.programmaticStreamSerializationAllowed = 1;
    cfg.attrs = attr;
    cfg.numAttrs = 1;
    cudaLaunchKernelEx(&cfg, func, args...);
}

// ---------------------------------------------------------------------------
// Host launch sequence (graph-capturable: kernel launches only)
// ---------------------------------------------------------------------------
extern "C" void kernel_launch(void* const* d_in, const int* in_sizes, int n_in,
                              void* d_out, int out_size)
{
    const float* features = (const float*)d_in[0];
    const float* cnn      = (const float*)d_in[1];
    const int*   captions = (const int*)  d_in[2];
    /* d_in[3] = lengths (unused: all T+1) */
    const float* embed    = (const float*)d_in[4];
    const float* W_ih     = (const float*)d_in[5];
    const float* W_hh     = (const float*)d_in[6];
    const float* b_ih     = (const float*)d_in[7];
    const float* b_hh     = (const float*)d_in[8];
    const float* W_attn   = (const float*)d_in[9];
    const float* b_attn   = (const float*)d_in[10];
    const float* W_attd   = (const float*)d_in[11];
    const float* b_attd   = (const float*)d_in[12];
    const float* W_out    = (const float*)d_in[13];
    const float* b_out    = (const float*)d_in[14];
    float* out = (float*)d_out;

    float* buf = nullptr;
    cudaGetSymbolAddress((void**)&buf, g_buf);
    __nv_bfloat16 *xs_bf, *wattn_bf, *wattd_bf, *h_bf, *x2_bf, *att_bf;
    __nv_bfloat16 *wcomb_bf, *wih_bf, *wattd2_bf;
    __half *hid_h, *wout_h;
    cudaGetSymbolAddress((void**)&xs_bf,     g_xs_bf);
    cudaGetSymbolAddress((void**)&wattn_bf,  g_wattn_bf);
    cudaGetSymbolAddress((void**)&wattd_bf,  g_wattd_bf);
    cudaGetSymbolAddress((void**)&h_bf,      g_h_bf);
    cudaGetSymbolAddress((void**)&att_bf,    g_att_bf);
    cudaGetSymbolAddress((void**)&x2_bf,     g_x2_bf);
    cudaGetSymbolAddress((void**)&wcomb_bf,  g_wcomb_bf);
    cudaGetSymbolAddress((void**)&wih_bf,    g_wih_bf);
    cudaGetSymbolAddress((void**)&wattd2_bf, g_wattd2_bf);
    cudaGetSymbolAddress((void**)&hid_h,     g_hid_h);
    cudaGetSymbolAddress((void**)&wout_h,    g_wout_h);

    cudaFuncSetAttribute(hmma_gemm<KBF, false>,
                         cudaFuncAttributeMaxDynamicSharedMemorySize, HSMEM);
    cudaFuncSetAttribute(hmma_gemm<KH1, true>,
                         cudaFuncAttributeMaxDynamicSharedMemorySize, HSMEM);
    cudaFuncSetAttribute(hmma_rec,
                         cudaFuncAttributeMaxDynamicSharedMemorySize, HSMEM);

    float* pan  = buf + PAN_OFF;
    float* pad  = buf + PAD_OFF;
    float* cbuf = buf + C_OFF;
    float* slC  = buf + SLC_OFF;
    float* slD  = buf + SLD_OFF;
    float* slG  = buf + SLG_OFF;
    float* bsum = buf + BS_OFF;

    // prep (no slab zero-fill) + fused xs build/split
    pdl_launch(k_prep, dim3(2048), dim3(256), 0,
               b_ih, b_hh, W_attn, W_hh, W_ih, W_attd);
    pdl_launch(k_build_xs_bf, dim3(2048), dim3(256), 0,
               features, captions, embed);

    // weight conversions
    pdl_launch(k_split_b, dim3(2048), dim3(256), 0,
               W_attn, (int)(E + H), wattn_bf, (int)A, (int)A);
    pdl_launch(k_split_b, dim3(1024), dim3(256), 0,
               W_attd, (int)(E + A), wattd_bf, (int)E, (int)E);
    pdl_launch(k_split_b16, dim3(4096), dim3(256), 0,
               W_out, (int)H, wout_h, (int)V, (int)VPAD);

    // pan[t] = x_t @ W_attn[:, :E]^T + b_attn  (bf16 3-term)
    pdl_launch(hmma_gemm<KBF, false>, dim3(A / 128, MALL / 128), dim3(256),
               (size_t)HSMEM, pan, (int)A, (int)A,
               (const uint16_t*)xs_bf, (const uint16_t*)wattn_bf, b_attn);
    // pad[t] = x_t @ W_attd[:, :E]^T + b_attd  (bf16 3-term)
    pdl_launch(hmma_gemm<KBF, false>, dim3(E / 128, MALL / 128), dim3(256),
               (size_t)HSMEM, pad, (int)E, (int)E,
               (const uint16_t*)xs_bf, (const uint16_t*)wattd_bf, b_attd);

    const int NLSTM = (B*H + 255)/256;

    // t = 0: gate_x = xs0 @ W_ih^T (xs_bf rows 0..127); lstm skips comb slabs
    pdl_launch(hmma_rec, dim3(G4/128, 1, 8), dim3(256), (size_t)HSMEM,
               slG, (int)G4, (const uint16_t*)xs_bf,
               (const uint16_t*)wih_bf, (int)KBF, (int)(KBF/8));
    pdl_launch(k_lstm_red, dim3(NLSTM), dim3(256), 0,
               (const float*)slC, (const float*)slG, (const float*)bsum,
               cbuf, hid_h, 0);

    // t = 1..T
    for (int t = 1; t <= T; ++t) {
        // comb: [scores | gates_h] = h @ Wcomb^T  (splitK4 -> 128 blocks)
        pdl_launch(hmma_rec, dim3(NC/128, 1, 4), dim3(256), (size_t)HSMEM,
                   slC, (int)NC, (const uint16_t*)h_bf,
                   (const uint16_t*)wcomb_bf, (int)KBF, (int)(KBF/4));

        // softmax(pan[t] + slabs) * cnn -> att_bf
        pdl_launch(k_softmax_att, dim3(B), dim3(256), 0,
                   (const float*)(pan + (size_t)t*B*A), (const float*)slC, cnn);

        // attd: slD[z] = att @ W_attd[:, E:]^T  (splitK32 -> 128 blocks)
        pdl_launch(hmma_rec, dim3(E/128, 1, 32), dim3(256), (size_t)HSMEM,
                   slD, (int)E, (const uint16_t*)att_bf,
                   (const uint16_t*)wattd2_bf, (int)KBFA, (int)(KBFA/32));

        // x2 = pad[t] + sum slD -> x2_bf
        pdl_launch(k_reduce_attd, dim3((B*E + 255)/256), dim3(256), 0,
                   (const float*)(pad + (size_t)t*B*E), (const float*)slD);

        // gate_x: slG = x2 @ W_ih^T  (splitK8 -> 128 blocks)
        pdl_launch(hmma_rec, dim3(G4/128, 1, 8), dim3(256), (size_t)HSMEM,
                   slG, (int)G4, (const uint16_t*)x2_bf,
                   (const uint16_t*)wih_bf, (int)KBF, (int)(KBF/8));

        // LSTM pointwise; h -> split-bf16 + fp16 row t
        pdl_launch(k_lstm_red, dim3(NLSTM), dim3(256), 0,
                   (const float*)slC, (const float*)slG, (const float*)bsum,
                   cbuf, hid_h + (size_t)t*B*KH1, 4);
    }

    // logits = hidden @ W_out^T + b_out  (fp16 1-term, K=512)
    pdl_launch(hmma_gemm<KH1, true>, dim3(VPAD / 128, MALL / 128), dim3(256),
               (size_t)HSMEM, out, (int)V, (int)V,
               (const uint16_t*)hid_h, (const uint16_t*)wout_h, b_out);
}

// round 16
// speedup vs baseline: 1.3022x; 1.1936x over previous
#include <cuda_runtime.h>
#include <cuda_bf16.h>
#include <cuda_fp16.h>
#include <math.h>
#include <stdint.h>
#include <utility>

// ---------------------------------------------------------------------------
// Problem constants
// ---------------------------------------------------------------------------
namespace {
constexpr int B   = 128;
constexpr int T   = 31;
constexpr int TP1 = 32;     // T+1
constexpr int E   = 512;
constexpr int H   = 512;
constexpr int V   = 10000;
constexpr int A   = 2048;
constexpr int G4  = 2048;   // 4*H
constexpr int NC  = 4096;   // comb cols: [scores | gates_h]
constexpr int MALL = TP1 * B;   // 4096
constexpr int VPAD = 10240;     // 80 * 128
constexpr int KH2  = 1024;      // 2-term fp16 K (A=[hi|lo], B=[hi|hi])
constexpr int KHA  = 4096;      // 2-term fp16 K for attd (Korig=2048)
constexpr int KH1  = 512;       // 1-term fp16 K (logits)

// fp32 scratch layout
constexpr size_t PAN_OFF  = 0;                              // [TP1][B][A]
constexpr size_t PAD_OFF  = PAN_OFF + (size_t)TP1*B*A;      // [TP1][B][E]
constexpr size_t C_OFF    = PAD_OFF + (size_t)TP1*B*E;      // [B][H]
constexpr size_t SLC_OFF  = C_OFF   + (size_t)B*H;          // [4][B][NC]
constexpr size_t SLD_OFF  = SLC_OFF + (size_t)4*B*NC;       // [32][B][E]
constexpr size_t SLG_OFF  = SLD_OFF + (size_t)32*B*E;       // [8][B][G4]
constexpr size_t BS_OFF   = SLG_OFF + (size_t)8*B*G4;       // [G4]
constexpr size_t BUF_TOTAL = BS_OFF + (size_t)G4;
}

__device__ float g_buf[BUF_TOTAL];

// fp16 2-term operand buffers (A-side [hi|lo], B-side [hi|hi])
__device__ __half g_xs_h   [(size_t)MALL * KH2];
__device__ __half g_wattn_h[(size_t)A * KH2];
__device__ __half g_wattd_h[(size_t)E * KH2];
__device__ __half g_h_h    [(size_t)B * KH2];
__device__ __half g_att_h  [(size_t)B * KHA];
__device__ __half g_x2_h   [(size_t)B * KH2];
__device__ __half g_wcomb_h[(size_t)NC * KH2];
__device__ __half g_wih_h  [(size_t)G4 * KH2];
__device__ __half g_wattd2_h[(size_t)E * KHA];
// fp16 1-term buffers (logits)
__device__ __half g_hid_h [(size_t)MALL * KH1];
__device__ __half g_wout_h[(size_t)VPAD * KH1];

__device__ __forceinline__ void pdl_wait() {
    asm volatile("griddepcontrol.wait;" ::: "memory");
}

__device__ __forceinline__ void split_h(float x, __half& hi, __half& lo) {
    hi = __float2half(x);
    lo = __float2half(x - __half2float(hi));
}

// ---------------------------------------------------------------------------
// HMMA helpers (sm_80+ PTX)
// ---------------------------------------------------------------------------
__device__ __forceinline__ uint32_t smem_u32(const void* p) {
    uint32_t a;
    asm("{ .reg .u64 t; cvta.to.shared.u64 t, %1; cvt.u32.u64 %0, t; }"
        : "=r"(a) : "l"(p));
    return a;
}
__device__ __forceinline__ void cpa16(uint32_t s, const void* g) {
    asm volatile("cp.async.cg.shared.global [%0], [%1], 16;"
                 :: "r"(s), "l"(g));
}
#define CP_COMMIT() asm volatile("cp.async.commit_group;" ::: "memory")
#define CP_WAIT(N)  asm volatile("cp.async.wait_group %0;" :: "n"(N) : "memory")

#define LDSM4(R0, R1, R2, R3, ADDR) \
    asm volatile("ldmatrix.sync.aligned.m8n8.x4.shared.b16 {%0,%1,%2,%3}, [%4];" \
        : "=r"(R0), "=r"(R1), "=r"(R2), "=r"(R3) : "r"(ADDR))

__device__ __forceinline__ void mma16816h(float* d, const uint32_t* a,
                                          uint32_t b0, uint32_t b1) {
    asm volatile(
        "mma.sync.aligned.m16n8k16.row.col.f32.f16.f16.f32 "
        "{%0,%1,%2,%3}, {%4,%5,%6,%7}, {%8,%9}, {%0,%1,%2,%3};"
        : "+f"(d[0]), "+f"(d[1]), "+f"(d[2]), "+f"(d[3])
        : "r"(a[0]), "r"(a[1]), "r"(a[2]), "r"(a[3]), "r"(b0), "r"(b1));
}

namespace {
constexpr int HBK   = 32;
constexpr int HROWB = 80;            // 32 elems * 2B + 16B pad
constexpr int HSTG  = 256 * HROWB;   // 20480 B per stage
constexpr int HSMEM = 3 * HSTG;      // 61440 B
}

// ---------------------------------------------------------------------------
// hmma_gemm: big parallel GEMMs (pan/pad/logits). 128x128, 2 CTA/SM.
// ---------------------------------------------------------------------------
template<int KTOT>
__global__ void __launch_bounds__(256, 2)
hmma_gemm(float* __restrict__ C, int ldc, int Nreal,
          const uint16_t* __restrict__ Abf,
          const uint16_t* __restrict__ Bbf,
          const float* __restrict__ bias)
{
    pdl_wait();
    constexpr int NT = KTOT / HBK;
    extern __shared__ __align__(16) char sm[];
    const uint32_t sb = smem_u32(sm);

    const int tid  = threadIdx.x;
    const int wid  = tid >> 5;
    const int lane = tid & 31;
    const int wm   = wid & 1;
    const int wn   = wid >> 1;
    const int row0 = blockIdx.y * 128;
    const int col0 = blockIdx.x * 128;

    const int qr0 = (tid)       >> 2, qc0 = (tid)       & 3;
    const int qr1 = (tid + 256) >> 2, qc1 = (tid + 256) & 3;

    auto LOADG = [&](int t, int stg) {
        const int k0 = t * HBK;
        const uint32_t sa  = sb + stg * HSTG;
        const uint32_t sbm = sa + 128 * HROWB;
        cpa16(sa  + qr0 * HROWB + qc0 * 16,
              Abf + (size_t)(row0 + qr0) * KTOT + k0 + qc0 * 8);
        cpa16(sa  + qr1 * HROWB + qc1 * 16,
              Abf + (size_t)(row0 + qr1) * KTOT + k0 + qc1 * 8);
        cpa16(sbm + qr0 * HROWB + qc0 * 16,
              Bbf + (size_t)(col0 + qr0) * KTOT + k0 + qc0 * 8);
        cpa16(sbm + qr1 * HROWB + qc1 * 16,
              Bbf + (size_t)(col0 + qr1) * KTOT + k0 + qc1 * 8);
    };

    float acc[4][4][4];
#pragma unroll
    for (int i = 0; i < 4; ++i)
#pragma unroll
        for (int j = 0; j < 4; ++j)
#pragma unroll
            for (int q = 0; q < 4; ++q) acc[i][j][q] = 0.f;

    const int lr  = lane & 15;
    const int lkb = (lane >> 4) * 16;

    LOADG(0, 0); CP_COMMIT();
    LOADG(1, 1); CP_COMMIT();

    for (int t = 0; t < NT; ++t) {
        if (t + 1 < NT) { CP_WAIT(1); } else { CP_WAIT(0); }
        __syncthreads();
        if (t + 2 < NT) { LOADG(t + 2, (t + 2) % 3); CP_COMMIT(); }

        const uint32_t aB = sb + (t % 3) * HSTG;
        const uint32_t bB = aB + 128 * HROWB;
#pragma unroll
        for (int ks = 0; ks < 2; ++ks) {
            const int kbyte = ks * 32 + lkb;
            uint32_t af[4][4];
#pragma unroll
            for (int mf = 0; mf < 4; ++mf)
                LDSM4(af[mf][0], af[mf][1], af[mf][2], af[mf][3],
                      aB + (wm * 64 + mf * 16 + lr) * HROWB + kbyte);
            uint32_t bfr[2][4];
#pragma unroll
            for (int p = 0; p < 2; ++p)
                LDSM4(bfr[p][0], bfr[p][1], bfr[p][2], bfr[p][3],
                      bB + (wn * 32 + p * 16 + lr) * HROWB + kbyte);
#pragma unroll
            for (int mf = 0; mf < 4; ++mf)
#pragma unroll
                for (int nf = 0; nf < 4; ++nf)
                    mma16816h(acc[mf][nf], af[mf],
                              bfr[nf >> 1][nf & 1], bfr[nf >> 1][(nf & 1) + 2]);
        }
    }

    const int rbase = row0 + wm * 64 + (lane >> 2);
    const int cbase = col0 + wn * 32 + 2 * (lane & 3);
#pragma unroll
    for (int nf = 0; nf < 4; ++nf) {
        const int col = cbase + nf * 8;
        if (col >= Nreal) continue;
        const float2 bv = *reinterpret_cast<const float2*>(bias + col);
#pragma unroll
        for (int mf = 0; mf < 4; ++mf) {
            const int r = rbase + mf * 16;
            *reinterpret_cast<float2*>(C + (size_t)r * ldc + col) =
                make_float2(acc[mf][nf][0] + bv.x, acc[mf][nf][1] + bv.y);
            *reinterpret_cast<float2*>(C + (size_t)(r + 8) * ldc + col) =
                make_float2(acc[mf][nf][2] + bv.x, acc[mf][nf][3] + bv.y);
        }
    }
}

// ---------------------------------------------------------------------------
// hmma_rec: recurrent-step GEMM. M = 128, runtime K range, split-K slabs.
// ---------------------------------------------------------------------------
__global__ void __launch_bounds__(256, 2)
hmma_rec(float* __restrict__ C, int N,
         const uint16_t* __restrict__ Abf,
         const uint16_t* __restrict__ Bbf, int lda,
         int KC)
{
    pdl_wait();
    extern __shared__ __align__(16) char sm[];
    const uint32_t sb = smem_u32(sm);

    const int NT   = KC / HBK;
    const int kbeg = blockIdx.z * KC;
    const int tid  = threadIdx.x;
    const int wid  = tid >> 5;
    const int lane = tid & 31;
    const int wm   = wid & 1;
    const int wn   = wid >> 1;
    const int col0 = blockIdx.x * 128;
    float* Cz = C + (size_t)blockIdx.z * 128 * N;

    const int qr0 = (tid)       >> 2, qc0 = (tid)       & 3;
    const int qr1 = (tid + 256) >> 2, qc1 = (tid + 256) & 3;

    auto LOADG = [&](int t, int stg) {
        const int k0 = kbeg + t * HBK;
        const uint32_t sa  = sb + stg * HSTG;
        const uint32_t sbm = sa + 128 * HROWB;
        cpa16(sa  + qr0 * HROWB + qc0 * 16,
              Abf + (size_t)qr0 * lda + k0 + qc0 * 8);
        cpa16(sa  + qr1 * HROWB + qc1 * 16,
              Abf + (size_t)qr1 * lda + k0 + qc1 * 8);
        cpa16(sbm + qr0 * HROWB + qc0 * 16,
              Bbf + (size_t)(col0 + qr0) * lda + k0 + qc0 * 8);
        cpa16(sbm + qr1 * HROWB + qc1 * 16,
              Bbf + (size_t)(col0 + qr1) * lda + k0 + qc1 * 8);
    };

    float acc[4][4][4];
#pragma unroll
    for (int i = 0; i < 4; ++i)
#pragma unroll
        for (int j = 0; j < 4; ++j)
#pragma unroll
            for (int q = 0; q < 4; ++q) acc[i][j][q] = 0.f;

    const int lr  = lane & 15;
    const int lkb = (lane >> 4) * 16;

    LOADG(0, 0); CP_COMMIT();
    LOADG(1, 1); CP_COMMIT();

    for (int t = 0; t < NT; ++t) {
        if (t + 1 < NT) { CP_WAIT(1); } else { CP_WAIT(0); }
        __syncthreads();
        if (t + 2 < NT) { LOADG(t + 2, (t + 2) % 3); CP_COMMIT(); }

        const uint32_t aB = sb + (t % 3) * HSTG;
        const uint32_t bB = aB + 128 * HROWB;
#pragma unroll
        for (int ks = 0; ks < 2; ++ks) {
            const int kbyte = ks * 32 + lkb;
            uint32_t af[4][4];
#pragma unroll
            for (int mf = 0; mf < 4; ++mf)
                LDSM4(af[mf][0], af[mf][1], af[mf][2], af[mf][3],
                      aB + (wm * 64 + mf * 16 + lr) * HROWB + kbyte);
            uint32_t bfr[2][4];
#pragma unroll
            for (int p = 0; p < 2; ++p)
                LDSM4(bfr[p][0], bfr[p][1], bfr[p][2], bfr[p][3],
                      bB + (wn * 32 + p * 16 + lr) * HROWB + kbyte);
#pragma unroll
            for (int mf = 0; mf < 4; ++mf)
#pragma unroll
                for (int nf = 0; nf < 4; ++nf)
                    mma16816h(acc[mf][nf], af[mf],
                              bfr[nf >> 1][nf & 1], bfr[nf >> 1][(nf & 1) + 2]);
        }
    }

    const int rbase = wm * 64 + (lane >> 2);
    const int cbase = col0 + wn * 32 + 2 * (lane & 3);
#pragma unroll
    for (int nf = 0; nf < 4; ++nf) {
        const int col = cbase + nf * 8;
#pragma unroll
        for (int mf = 0; mf < 4; ++mf) {
            const int r = rbase + mf * 16;
            *reinterpret_cast<float2*>(Cz + (size_t)r * N + col) =
                make_float2(acc[mf][nf][0], acc[mf][nf][1]);
            *reinterpret_cast<float2*>(Cz + (size_t)(r + 8) * N + col) =
                make_float2(acc[mf][nf][2], acc[mf][nf][3]);
        }
    }
}

// ---------------------------------------------------------------------------
// Conversion kernels
// ---------------------------------------------------------------------------
// Fused xs build + fp16 2-term split: A-side [hi|lo], K=1024.
__global__ void k_build_xs_h(const float* __restrict__ features,
                             const int*   __restrict__ captions,
                             const float* __restrict__ embed)
{
    pdl_wait();
    int idx = blockIdx.x * blockDim.x + threadIdx.x;
    int stride = gridDim.x * blockDim.x;
    for (int i = idx; i < TP1*B*E; i += stride) {
        int e  = i & (E - 1);
        int be = i >> 9;
        int b  = be & (B - 1);
        int t  = be >> 7;
        float v;
        if (t == 0) {
            v = features[b*E + e];
        } else {
            int tok = captions[b*T + (t - 1)];
            v = embed[(size_t)tok*E + e];
        }
        __half hi, lo;
        split_h(v, hi, lo);
        __half* d = g_xs_h + (size_t)(t * B + b) * KH2;
        d[e] = hi; d[e + 512] = lo;
    }
}

// B-side fp16 2-term: [hi | hi], Korig=512
__global__ void k_split_bh(const float* __restrict__ src, int ld,
                           __half* __restrict__ dst, int Nreal, int Npad)
{
    pdl_wait();
    int i = blockIdx.x * blockDim.x + threadIdx.x;
    int n = Npad * 512;
    for (; i < n; i += gridDim.x * blockDim.x) {
        int r = i >> 9, j = i & 511;
        float x = (r < Nreal) ? src[(size_t)r * ld + j] : 0.f;
        __half hi = __float2half(x);
        __half* d = dst + (size_t)r * KH2;
        d[j] = hi; d[j + 512] = hi;
    }
}

// fp16 1-term (W_out)
__global__ void k_split_b16(const float* __restrict__ src, int ld,
                            __half* __restrict__ dst, int Nreal, int Npad)
{
    pdl_wait();
    int i = blockIdx.x * blockDim.x + threadIdx.x;
    int n = Npad * 512;
    for (; i < n; i += gridDim.x * blockDim.x) {
        int r = i >> 9, j = i & 511;
        float x = (r < Nreal) ? src[(size_t)r * ld + j] : 0.f;
        dst[(size_t)r * KH1 + j] = __float2half(x);
    }
}

// ---------------------------------------------------------------------------
// Prep: zero c, fuse biases, build fp16 B-side weights for the recurrence
// ---------------------------------------------------------------------------
__global__ void k_prep(const float* __restrict__ b_ih, const float* __restrict__ b_hh,
                       const float* __restrict__ W_attn, const float* __restrict__ W_hh,
                       const float* __restrict__ W_ih, const float* __restrict__ W_attd)
{
    int idx = blockIdx.x * blockDim.x + threadIdx.x;
    int stride = gridDim.x * blockDim.x;
    for (int i = idx; i < B*H; i += stride)
        g_buf[C_OFF + i] = 0.f;
    for (int i = idx; i < G4; i += stride)
        g_buf[BS_OFF + i] = b_ih[i] + b_hh[i];
    // Wcomb_h [4096][1024]: rows 0..2047 = W_attn[:, E:], rows 2048.. = W_hh
    for (int i = idx; i < NC*512; i += stride) {
        int r = i >> 9, k = i & 511;
        float x = (r < A) ? W_attn[(size_t)r*(E+H) + E + k]
                          : W_hh[(size_t)(r - A)*H + k];
        __half hi = __float2half(x);
        __half* d = g_wcomb_h + (size_t)r * KH2;
        d[k] = hi; d[k + 512] = hi;
    }
    // Wih_h [2048][1024]
    for (int i = idx; i < G4*512; i += stride) {
        int r = i >> 9, k = i & 511;
        __half hi = __float2half(W_ih[(size_t)r*E + k]);
        __half* d = g_wih_h + (size_t)r * KH2;
        d[k] = hi; d[k + 512] = hi;
    }
    // Wattd2_h [512][4096] from W_attd[:, E:] (Korig = 2048)
    for (int i = idx; i < E*2048; i += stride) {
        int r = i >> 11, k = i & 2047;
        __half hi = __float2half(W_attd[(size_t)r*(E+A) + E + k]);
        __half* d = g_wattd2_h + (size_t)r * KHA;
        d[k] = hi; d[k + 2048] = hi;
    }
}

// ---------------------------------------------------------------------------
// softmax(pan[t] + 4 comb slabs cols[0:A]) * cnn -> att_h (fp16 A-side [hi|lo])
// ---------------------------------------------------------------------------
__global__ void __launch_bounds__(256)
k_softmax_att(const float* __restrict__ pre,
              const float* __restrict__ slc,
              const float* __restrict__ cnn)
{
    pdl_wait();
    int b = blockIdx.x;
    int t = threadIdx.x;
    const size_t o0 = (size_t)b*A;
    const float* s0 = slc + (size_t)b*NC;
    const size_t SS = (size_t)B*NC;
    float v[8];
    float mx = -1e30f;
#pragma unroll
    for (int i = 0; i < 8; ++i) {
        int j = t + 256*i;
        float s = pre[o0 + j] + s0[j] + s0[j + SS] + s0[j + 2*SS] + s0[j + 3*SS];
        v[i] = s;
        mx = fmaxf(mx, s);
    }
    __shared__ float red[256];
    red[t] = mx; __syncthreads();
    for (int off = 128; off > 0; off >>= 1) {
        if (t < off) red[t] = fmaxf(red[t], red[t + off]);
        __syncthreads();
    }
    mx = red[0]; __syncthreads();

    float sum = 0.f;
#pragma unroll
    for (int i = 0; i < 8; ++i) {
        v[i] = expf(v[i] - mx);
        sum += v[i];
    }
    red[t] = sum; __syncthreads();
    for (int off = 128; off > 0; off >>= 1) {
        if (t < off) red[t] += red[t + off];
        __syncthreads();
    }
    float inv = 1.f / red[0];

    const float* cb = cnn + o0;
    __half* ab = g_att_h + (size_t)b * KHA;
#pragma unroll
    for (int i = 0; i < 8; ++i) {
        int j = t + 256*i;
        float x = cb[j] * v[i] * inv;
        __half hi, lo;
        split_h(x, hi, lo);
        ab[j] = hi; ab[j + 2048] = lo;
    }
}

// x2 = pad[t] + sum of 32 slD slabs -> x2_h (fp16 A-side [hi|lo])
__global__ void __launch_bounds__(256)
k_reduce_attd(const float* __restrict__ pre,
              const float* __restrict__ slab)
{
    pdl_wait();
    int i = blockIdx.x * blockDim.x + threadIdx.x;
    if (i >= B*E) return;
    float s = pre[i];
#pragma unroll
    for (int z = 0; z < 32; ++z) s += slab[i + (size_t)z*B*E];
    int b = i >> 9, j = i & 511;
    __half hi, lo;
    split_h(s, hi, lo);
    __half* d = g_x2_h + (size_t)b * KH2;
    d[j] = hi; d[j + 512] = lo;
}

// LSTM pointwise: gates = bsum + ncomb comb slabs (cols A..) + 8 gate_x slabs.
__global__ void __launch_bounds__(256)
k_lstm_red(const float* __restrict__ slc,
           const float* __restrict__ slg,
           const float* __restrict__ bsum,
           float* __restrict__ c,
           __half* __restrict__ hid16,
           int ncomb)
{
    pdl_wait();
    int idx = blockIdx.x * blockDim.x + threadIdx.x;
    if (idx >= B*H) return;
    int b = idx >> 9;
    int j = idx & 511;
    float gi = bsum[j], gf = bsum[j + 512], gg = bsum[j + 1024], go = bsum[j + 1536];
    for (int z = 0; z < ncomb; ++z) {
        const float* gc = slc + (size_t)z*B*NC + (size_t)b*NC + A;
        gi += gc[j];  gf += gc[j + 512];
        gg += gc[j + 1024];  go += gc[j + 1536];
    }
#pragma unroll
    for (int z = 0; z < 8; ++z) {
        const float* gx = slg + (size_t)z*B*G4 + (size_t)b*G4;
        gi += gx[j];  gf += gx[j + 512];
        gg += gx[j + 1024];  go += gx[j + 1536];
    }
    float ig = 1.f / (1.f + expf(-gi));
    float fg = 1.f / (1.f + expf(-gf));
    float gt = tanhf(gg);
    float og = 1.f / (1.f + expf(-go));
    float cn = fg * c[idx] + ig * gt;
    float hn = og * tanhf(cn);
    c[idx] = cn;
    __half hi, lo;
    split_h(hn, hi, lo);
    __half* d = g_h_h + (size_t)b * KH2;
    d[j] = hi; d[j + 512] = lo;
    hid16[(size_t)b * KH1 + j] = hi;
}

// ---------------------------------------------------------------------------
// Host: PDL launch helper
// ---------------------------------------------------------------------------
template<typename F, typename... Args>
static inline void pdl_launch(F func, dim3 gd, dim3 bd, size_t sh, Args... args)
{
    cudaLaunchConfig_t cfg = {};
    cfg.gridDim = gd;
    cfg.blockDim = bd;
    cfg.dynamicSmemBytes = sh;
    cudaLaunchAttribute attr[1];
    attr[0].id = cudaLaunchAttributeProgrammaticStreamSerialization;
    attr[0].val.programmaticStreamSerializationAllowed = 1;
    cfg.attrs = attr;
    cfg.numAttrs = 1;
    cudaLaunchKernelEx(&cfg, func, args...);
}

// ---------------------------------------------------------------------------
// Host launch sequence (graph-capturable: kernel launches only)
// ---------------------------------------------------------------------------
extern "C" void kernel_launch(void* const* d_in, const int* in_sizes, int n_in,
                              void* d_out, int out_size)
{
    const float* features = (const float*)d_in[0];
    const float* cnn      = (const float*)d_in[1];
    const int*   captions = (const int*)  d_in[2];
    /* d_in[3] = lengths (unused: all T+1) */
    const float* embed    = (const float*)d_in[4];
    const float* W_ih     = (const float*)d_in[5];
    const float* W_hh     = (const float*)d_in[6];
    const float* b_ih     = (const float*)d_in[7];
    const float* b_hh     = (const float*)d_in[8];
    const float* W_attn   = (const float*)d_in[9];
    const float* b_attn   = (const float*)d_in[10];
    const float* W_attd   = (const float*)d_in[11];
    const float* b_attd   = (const float*)d_in[12];
    const float* W_out    = (const float*)d_in[13];
    const float* b_out    = (const float*)d_in[14];
    float* out = (float*)d_out;

    float* buf = nullptr;
    cudaGetSymbolAddress((void**)&buf, g_buf);
    __half *xs_h, *wattn_h, *wattd_h, *h_h, *x2_h, *att_h;
    __half *wcomb_h, *wih_h, *wattd2_h;
    __half *hid_h, *wout_h;
    cudaGetSymbolAddress((void**)&xs_h,     g_xs_h);
    cudaGetSymbolAddress((void**)&wattn_h,  g_wattn_h);
    cudaGetSymbolAddress((void**)&wattd_h,  g_wattd_h);
    cudaGetSymbolAddress((void**)&h_h,      g_h_h);
    cudaGetSymbolAddress((void**)&att_h,    g_att_h);
    cudaGetSymbolAddress((void**)&x2_h,     g_x2_h);
    cudaGetSymbolAddress((void**)&wcomb_h,  g_wcomb_h);
    cudaGetSymbolAddress((void**)&wih_h,    g_wih_h);
    cudaGetSymbolAddress((void**)&wattd2_h, g_wattd2_h);
    cudaGetSymbolAddress((void**)&hid_h,    g_hid_h);
    cudaGetSymbolAddress((void**)&wout_h,   g_wout_h);

    cudaFuncSetAttribute(hmma_gemm<KH2>,
                         cudaFuncAttributeMaxDynamicSharedMemorySize, HSMEM);
    cudaFuncSetAttribute(hmma_gemm<KH1>,
                         cudaFuncAttributeMaxDynamicSharedMemorySize, HSMEM);
    cudaFuncSetAttribute(hmma_rec,
                         cudaFuncAttributeMaxDynamicSharedMemorySize, HSMEM);

    float* pan  = buf + PAN_OFF;
    float* pad  = buf + PAD_OFF;
    float* cbuf = buf + C_OFF;
    float* slC  = buf + SLC_OFF;
    float* slD  = buf + SLD_OFF;
    float* slG  = buf + SLG_OFF;
    float* bsum = buf + BS_OFF;

    // prep + fused xs build/split
    pdl_launch(k_prep, dim3(2048), dim3(256), 0,
               b_ih, b_hh, W_attn, W_hh, W_ih, W_attd);
    pdl_launch(k_build_xs_h, dim3(2048), dim3(256), 0,
               features, captions, embed);

    // weight conversions
    pdl_launch(k_split_bh, dim3(2048), dim3(256), 0,
               W_attn, (int)(E + H), wattn_h, (int)A, (int)A);
    pdl_launch(k_split_bh, dim3(1024), dim3(256), 0,
               W_attd, (int)(E + A), wattd_h, (int)E, (int)E);
    pdl_launch(k_split_b16, dim3(4096), dim3(256), 0,
               W_out, (int)H, wout_h, (int)V, (int)VPAD);

    // pan[t] = x_t @ W_attn[:, :E]^T + b_attn  (fp16 2-term, K=1024)
    pdl_launch(hmma_gemm<KH2>, dim3(A / 128, MALL / 128), dim3(256),
               (size_t)HSMEM, pan, (int)A, (int)A,
               (const uint16_t*)xs_h, (const uint16_t*)wattn_h, b_attn);
    // pad[t] = x_t @ W_attd[:, :E]^T + b_attd  (fp16 2-term, K=1024)
    pdl_launch(hmma_gemm<KH2>, dim3(E / 128, MALL / 128), dim3(256),
               (size_t)HSMEM, pad, (int)E, (int)E,
               (const uint16_t*)xs_h, (const uint16_t*)wattd_h, b_attd);

    const int NLSTM = (B*H + 255)/256;

    // t = 0: gate_x = xs0 @ W_ih^T (xs_h rows 0..127); lstm skips comb slabs
    pdl_launch(hmma_rec, dim3(G4/128, 1, 8), dim3(256), (size_t)HSMEM,
               slG, (int)G4, (const uint16_t*)xs_h,
               (const uint16_t*)wih_h, (int)KH2, (int)(KH2/8));
    pdl_launch(k_lstm_red, dim3(NLSTM), dim3(256), 0,
               (const float*)slC, (const float*)slG, (const float*)bsum,
               cbuf, hid_h, 0);

    // t = 1..T
    for (int t = 1; t <= T; ++t) {
        // comb: [scores | gates_h] = h @ Wcomb^T  (splitK4 -> 128 blocks)
        pdl_launch(hmma_rec, dim3(NC/128, 1, 4), dim3(256), (size_t)HSMEM,
                   slC, (int)NC, (const uint16_t*)h_h,
                   (const uint16_t*)wcomb_h, (int)KH2, (int)(KH2/4));

        // softmax(pan[t] + slabs) * cnn -> att_h
        pdl_launch(k_softmax_att, dim3(B), dim3(256), 0,
                   (const float*)(pan + (size_t)t*B*A), (const float*)slC, cnn);

        // attd: slD[z] = att @ W_attd[:, E:]^T  (splitK32 -> 128 blocks)
        pdl_launch(hmma_rec, dim3(E/128, 1, 32), dim3(256), (size_t)HSMEM,
                   slD, (int)E, (const uint16_t*)att_h,
                   (const uint16_t*)wattd2_h, (int)KHA, (int)(KHA/32));

        // x2 = pad[t] + sum slD -> x2_h
        pdl_launch(k_reduce_attd, dim3((B*E + 255)/256), dim3(256), 0,
                   (const float*)(pad + (size_t)t*B*E), (const float*)slD);

        // gate_x: slG = x2 @ W_ih^T  (splitK8 -> 128 blocks)
        pdl_launch(hmma_rec, dim3(G4/128, 1, 8), dim3(256), (size_t)HSMEM,
                   slG, (int)G4, (const uint16_t*)x2_h,
                   (const uint16_t*)wih_h, (int)KH2, (int)(KH2/8));

        // LSTM pointwise; h -> fp16 [hi|lo] + fp16 row t
        pdl_launch(k_lstm_red, dim3(NLSTM), dim3(256), 0,
                   (const float*)slC, (const float*)slG, (const float*)bsum,
                   cbuf, hid_h + (size_t)t*B*KH1, 4);
    }

    // logits = hidden @ W_out^T + b_out  (fp16 1-term, K=512)
    pdl_launch(hmma_gemm<KH1>, dim3(VPAD / 128, MALL / 128), dim3(256),
               (size_t)HSMEM, out, (int)V, (int)V,
               (const uint16_t*)hid_h, (const uint16_t*)wout_h, b_out);
}